// round 2
// baseline (speedup 1.0000x reference)
#include <cuda_runtime.h>
#include <math.h>
#include <stdint.h>

#define BB 4
#define LL 2048
#define DD 1024
#define HH 16
#define HDIM 64
#define KK 24
#define MLPD 4096
#define BL (BB*LL)
#define NF 4096

// ---------------- scratch (device globals; allocation-free) ----------------
__device__ float  g_xi[BL*DD];
__device__ float  g_xt[BL*DD];
__device__ float2 g_Ffilt[(size_t)DD*NF];
__device__ float  g_projt[BL*DD];
__device__ float  g_stu[BL*DD];
__device__ float  g_x1[BL*DD];
__device__ float  g_q[BL*DD];
__device__ float  g_k[BL*DD];
__device__ float  g_v[BL*DD];
__device__ float  g_scores[(size_t)BB*HH*LL*LL];   // 1 GB
__device__ float  g_att[BL*DD];
__device__ float  g_xres[BL*DD];
__device__ float  g_y1[BL*DD];
__device__ float  g_h[(size_t)BL*MLPD];

// ---------------- helpers ----------------
__device__ __forceinline__ float gelu_f(float x) {
    float x3 = x*x*x;
    return 0.5f*x*(1.0f + tanhf(0.7978845608028654f*(x + 0.044715f*x3)));
}

__device__ __forceinline__ float block_sum256(float v) {
    __shared__ float red[8];
    int lane = threadIdx.x & 31, w = threadIdx.x >> 5;
    #pragma unroll
    for (int o = 16; o; o >>= 1) v += __shfl_xor_sync(0xffffffffu, v, o);
    __syncthreads();
    if (lane == 0) red[w] = v;
    __syncthreads();
    if (threadIdx.x == 0) {
        float s = 0.f;
        #pragma unroll
        for (int i = 0; i < 8; i++) s += red[i];
        red[0] = s;
    }
    __syncthreads();
    return red[0];
}

__device__ __forceinline__ float block_max256(float v) {
    __shared__ float red[8];
    int lane = threadIdx.x & 31, w = threadIdx.x >> 5;
    #pragma unroll
    for (int o = 16; o; o >>= 1) v = fmaxf(v, __shfl_xor_sync(0xffffffffu, v, o));
    __syncthreads();
    if (lane == 0) red[w] = v;
    __syncthreads();
    if (threadIdx.x == 0) {
        float s = red[0];
        #pragma unroll
        for (int i = 1; i < 8; i++) s = fmaxf(s, red[i]);
        red[0] = s;
    }
    __syncthreads();
    return red[0];
}

// ---------------- generic tiled SGEMM ----------------
// C = alpha*(A @ B[ᵀ]) (+bias[n]) (gelu) (+resid)  with 2-component batch strides
// mode bits: 1=bias, 2=gelu, 4=resid
template<int TB>
__global__ void __launch_bounds__(256) sgemm(
    const float* __restrict__ A, const float* __restrict__ Bm, float* __restrict__ C,
    int M, int N, int Kd, int lda, int ldb, int ldc,
    long long sA1, long long sA2, long long sB1, long long sB2,
    long long sC1, long long sC2, int bdiv,
    float alpha, const float* __restrict__ bias,
    const float* __restrict__ resid, int mode)
{
    __shared__ float As[8][132];
    __shared__ float Bs[8][132];

    int z  = blockIdx.z;
    int z1 = z / bdiv, z2 = z - z1*bdiv;
    A  += (long long)z1*sA1 + (long long)z2*sA2;
    Bm += (long long)z1*sB1 + (long long)z2*sB2;
    long long offC = (long long)z1*sC1 + (long long)z2*sC2;
    C  += offC;
    const float* R = (mode & 4) ? (resid + offC) : nullptr;

    int tid   = threadIdx.x;
    int mBase = blockIdx.y * 128, nBase = blockIdx.x * 128;
    int arow  = tid >> 1;
    int ac4   = (tid & 1) << 2;
    int brow  = tid >> 5;
    int bc4   = (tid & 31) << 2;
    int rb    = (tid >> 4) << 3;
    int cb    = (tid & 15) << 3;

    float acc[8][8];
    #pragma unroll
    for (int i = 0; i < 8; i++)
        #pragma unroll
        for (int j = 0; j < 8; j++) acc[i][j] = 0.f;

    for (int k0 = 0; k0 < Kd; k0 += 8) {
        float4 av = make_float4(0.f,0.f,0.f,0.f);
        if (mBase + arow < M)
            av = *(const float4*)(A + (long long)(mBase+arow)*lda + (k0 + ac4));
        As[ac4+0][arow] = av.x; As[ac4+1][arow] = av.y;
        As[ac4+2][arow] = av.z; As[ac4+3][arow] = av.w;

        if (TB == 0) {
            float4 bv = make_float4(0.f,0.f,0.f,0.f);
            if (nBase + bc4 < N)
                bv = *(const float4*)(Bm + (long long)(k0+brow)*ldb + (nBase + bc4));
            *(float4*)&Bs[brow][bc4] = bv;
        } else {
            float4 bv = make_float4(0.f,0.f,0.f,0.f);
            if (nBase + arow < N)
                bv = *(const float4*)(Bm + (long long)(nBase+arow)*ldb + (k0 + ac4));
            Bs[ac4+0][arow] = bv.x; Bs[ac4+1][arow] = bv.y;
            Bs[ac4+2][arow] = bv.z; Bs[ac4+3][arow] = bv.w;
        }
        __syncthreads();

        #pragma unroll
        for (int kk = 0; kk < 8; kk++) {
            float a[8], b[8];
            *(float4*)&a[0] = *(const float4*)&As[kk][rb];
            *(float4*)&a[4] = *(const float4*)&As[kk][rb+4];
            *(float4*)&b[0] = *(const float4*)&Bs[kk][cb];
            *(float4*)&b[4] = *(const float4*)&Bs[kk][cb+4];
            #pragma unroll
            for (int i = 0; i < 8; i++)
                #pragma unroll
                for (int j = 0; j < 8; j++)
                    acc[i][j] = fmaf(a[i], b[j], acc[i][j]);
        }
        __syncthreads();
    }

    bool hb = mode & 1, hg = mode & 2, hr = mode & 4;
    #pragma unroll
    for (int i = 0; i < 8; i++) {
        int m = mBase + rb + i;
        if (m >= M) continue;
        long long ro = (long long)m * ldc;
        #pragma unroll
        for (int j = 0; j < 8; j++) {
            int n = nBase + cb + j;
            if (n >= N) continue;
            float vv = acc[i][j] * alpha;
            if (hb) vv += bias[n];
            if (hg) vv = gelu_f(vv);
            if (hr) vv += R[ro + n];
            C[ro + n] = vv;
        }
    }
}

// ---------------- transpose [rows,cols] -> [cols,rows] per batch ----------------
__global__ void transpose_kernel(const float* __restrict__ in, float* __restrict__ out,
                                 int rows, int cols)
{
    __shared__ float t[32][33];
    long long bo = (long long)blockIdx.z * rows * cols;
    int c0 = blockIdx.x * 32, r0 = blockIdx.y * 32;
    int tx = threadIdx.x, ty = threadIdx.y;
    #pragma unroll
    for (int i = 0; i < 32; i += 8)
        t[ty+i][tx] = in[bo + (long long)(r0+ty+i)*cols + (c0+tx)];
    __syncthreads();
    #pragma unroll
    for (int i = 0; i < 32; i += 8)
        out[bo + (long long)(c0+ty+i)*rows + (r0+tx)] = t[tx][ty+i];
}

// ---------------- FFT (radix-2 DIT, n=4096, 512 threads) ----------------
__device__ __forceinline__ int rev12(int i) { return __brev(i) >> 20; }

__device__ __forceinline__ void tw_init(float2* tw, int tid) {
    for (int m = tid; m < 1024; m += 512) {
        float sv, cv;
        sincosf(-6.283185307179586f * (float)m / 4096.0f, &sv, &cv);
        tw[m] = make_float2(cv, sv);
    }
}

__device__ void do_fft(float2* s, const float2* tw, int tid) {
    #pragma unroll 1
    for (int lh = 0; lh < 12; lh++) {
        int half = 1 << lh;
        #pragma unroll 1
        for (int idx = tid; idx < NF/2; idx += 512) {
            int j   = idx & (half - 1);
            int pos = 2*idx - j;
            int m   = j << (11 - lh);
            float2 w;
            if (m & 1024) { float2 t = tw[m & 1023]; w = make_float2(t.y, -t.x); }
            else          { w = tw[m]; }
            float2 u = s[pos];
            float2 q = s[pos + half];
            float2 v = make_float2(w.x*q.x - w.y*q.y, w.x*q.y + w.y*q.x);
            s[pos]        = make_float2(u.x + v.x, u.y + v.y);
            s[pos + half] = make_float2(u.x - v.x, u.y - v.y);
        }
        __syncthreads();
    }
}

// filters[t,d] = sum_k eig_vecs[t,k]*eig_vals[k]^0.25*w_filters[k,d]; store FFT per d
__global__ void __launch_bounds__(512) filters_kernel(
    const float* __restrict__ eig_vals, const float* __restrict__ eig_vecs,
    const float* __restrict__ w_filters, float2* __restrict__ Ffilt)
{
    __shared__ float2 s[NF];
    __shared__ float2 tw[1024];
    __shared__ float  wk[KK];
    int d = blockIdx.x, tid = threadIdx.x;
    if (tid < KK) wk[tid] = powf(eig_vals[tid], 0.25f) * w_filters[tid*DD + d];
    tw_init(tw, tid);
    for (int i = tid; i < NF; i += 512) s[i] = make_float2(0.f, 0.f);
    __syncthreads();
    for (int t = tid; t < LL; t += 512) {
        float f = 0.f;
        #pragma unroll
        for (int k = 0; k < KK; k++) f += eig_vecs[t*KK + k] * wk[k];
        s[rev12(t)] = make_float2(f, 0.f);
    }
    __syncthreads();
    do_fft(s, tw, tid);
    for (int i = tid; i < NF; i += 512)
        Ffilt[(long long)d*NF + i] = s[i];
}

// per-(b,d) channel: FFT(xi) * Ffilt, IFFT, keep first L real samples
__global__ void __launch_bounds__(512) conv_kernel(
    const float* __restrict__ xt, const float2* __restrict__ Ffilt,
    float* __restrict__ projt)
{
    __shared__ float2 s[NF];
    __shared__ float2 tw[1024];
    int z = blockIdx.x, tid = threadIdx.x;
    int d = z & (DD - 1);
    long long base = (long long)z * LL;
    tw_init(tw, tid);
    for (int i = tid; i < NF; i += 512) s[i] = make_float2(0.f, 0.f);
    __syncthreads();
    for (int t = tid; t < LL; t += 512)
        s[rev12(t)] = make_float2(xt[base + t], 0.f);
    __syncthreads();
    do_fft(s, tw, tid);
    // multiply by filter spectrum, conjugate (IFFT via conj-FFT-conj)
    for (int i = tid; i < NF; i += 512) {
        float2 a = s[i];
        float2 f = Ffilt[(long long)d*NF + i];
        s[i] = make_float2(a.x*f.x - a.y*f.y, -(a.x*f.y + a.y*f.x));
    }
    __syncthreads();
    // bit-reverse permute back for second DIT pass
    float2 r[8];
    #pragma unroll
    for (int k = 0; k < 8; k++) r[k] = s[rev12(tid + k*512)];
    __syncthreads();
    #pragma unroll
    for (int k = 0; k < 8; k++) s[tid + k*512] = r[k];
    __syncthreads();
    do_fft(s, tw, tid);
    const float inv = 1.0f / 4096.0f;
    for (int l = tid; l < LL; l += 512)
        projt[base + l] = s[l].x * inv;
}

// ---------------- LayerNorm (one block per row of D=1024) ----------------
__global__ void __launch_bounds__(256) ln_kernel(
    const float* __restrict__ x, float* __restrict__ y,
    const float* __restrict__ sc, const float* __restrict__ bi)
{
    long long base = (long long)blockIdx.x * DD;
    int tid = threadIdx.x;
    float4 v = *(const float4*)(x + base + tid*4);
    float mean = block_sum256(v.x + v.y + v.z + v.w) * (1.0f/DD);
    float dx = v.x - mean, dy = v.y - mean, dz = v.z - mean, dw = v.w - mean;
    float var = block_sum256(dx*dx + dy*dy + dz*dz + dw*dw) * (1.0f/DD);
    float rstd = rsqrtf(var + 1e-6f);
    float4 s4 = *(const float4*)(sc + tid*4);
    float4 b4 = *(const float4*)(bi + tid*4);
    float4 o;
    o.x = dx*rstd*s4.x + b4.x;
    o.y = dy*rstd*s4.y + b4.y;
    o.z = dz*rstd*s4.z + b4.z;
    o.w = dw*rstd*s4.w + b4.w;
    *(float4*)(y + base + tid*4) = o;
}

// ---------------- softmax over rows of 2048 (in place) ----------------
__global__ void __launch_bounds__(256) softmax_kernel(float* __restrict__ S)
{
    long long base = (long long)blockIdx.x * LL;
    int tid = threadIdx.x;
    float v[8];
    float mx = -1e30f;
    #pragma unroll
    for (int k = 0; k < 8; k++) {
        v[k] = S[base + tid + k*256];
        mx = fmaxf(mx, v[k]);
    }
    mx = block_max256(mx);
    float lsum = 0.f;
    #pragma unroll
    for (int k = 0; k < 8; k++) { v[k] = expf(v[k] - mx); lsum += v[k]; }
    float inv = 1.0f / block_sum256(lsum);
    #pragma unroll
    for (int k = 0; k < 8; k++)
        S[base + tid + k*256] = v[k] * inv;
}

// ---------------- launch ----------------
static float* sym(const void* s) { void* p = nullptr; cudaGetSymbolAddress(&p, s); return (float*)p; }

extern "C" void kernel_launch(void* const* d_in, const int* in_sizes, int n_in,
                              void* d_out, int out_size)
{
    const float* inputs    = (const float*)d_in[0];
    const float* eig_vals  = (const float*)d_in[1];
    const float* eig_vecs  = (const float*)d_in[2];
    const float* w_filters = (const float*)d_in[3];
    const float* w_inputs  = (const float*)d_in[4];
    const float* ln1_s     = (const float*)d_in[5];
    const float* ln1_b     = (const float*)d_in[6];
    const float* wq        = (const float*)d_in[7];
    const float* wk        = (const float*)d_in[8];
    const float* wv        = (const float*)d_in[9];
    const float* wo        = (const float*)d_in[10];
    const float* ln2_s     = (const float*)d_in[11];
    const float* ln2_b     = (const float*)d_in[12];
    const float* mlp_w1    = (const float*)d_in[13];
    const float* mlp_b1    = (const float*)d_in[14];
    const float* mlp_w2    = (const float*)d_in[15];
    const float* mlp_b2    = (const float*)d_in[16];
    float* out = (float*)d_out;

    float*  xi     = sym(g_xi);
    float*  xt     = sym(g_xt);
    float2* Ffilt  = (float2*)sym(g_Ffilt);
    float*  projt  = sym(g_projt);
    float*  stu    = sym(g_stu);
    float*  x1     = sym(g_x1);
    float*  q      = sym(g_q);
    float*  kb     = sym(g_k);
    float*  vb     = sym(g_v);
    float*  sc     = sym(g_scores);
    float*  att    = sym(g_att);
    float*  xres   = sym(g_xres);
    float*  y1     = sym(g_y1);
    float*  hbuf   = sym(g_h);

    const long long LLD = (long long)LL * DD;     // batch stride in q/k/v/att
    const long long LL2 = (long long)LL * LL;

    // 1. filter spectrum per channel d
    filters_kernel<<<DD, 512>>>(eig_vals, eig_vecs, w_filters, Ffilt);

    // 2. xi = inputs @ w_inputs   [BL,D]
    sgemm<0><<<dim3(DD/128, BL/128, 1), 256>>>(inputs, w_inputs, xi,
        BL, DD, DD, DD, DD, DD, 0,0,0,0,0,0, 1, 1.0f, nullptr, nullptr, 0);

    // 3. transpose to [B,D,L] for coalesced FFT
    transpose_kernel<<<dim3(DD/32, LL/32, BB), dim3(32,8)>>>(xi, xt, LL, DD);

    // 4. spectral causal conv (FFT * filter * IFFT) per (b,d)
    conv_kernel<<<BB*DD, 512>>>(xt, Ffilt, projt);

    // 5. transpose back: stu_outs [B,L,D]
    transpose_kernel<<<dim3(LL/32, DD/32, BB), dim3(32,8)>>>(projt, stu, DD, LL);

    // 6. LN1
    ln_kernel<<<BL, 256>>>(stu, x1, ln1_s, ln1_b);

    // 7. Q (scaled 1/sqrt(hd)), K, V
    sgemm<0><<<dim3(8, 64, 1), 256>>>(x1, wq, q,
        BL, DD, DD, DD, DD, DD, 0,0,0,0,0,0, 1, 0.125f, nullptr, nullptr, 0);
    sgemm<0><<<dim3(8, 64, 1), 256>>>(x1, wk, kb,
        BL, DD, DD, DD, DD, DD, 0,0,0,0,0,0, 1, 1.0f, nullptr, nullptr, 0);
    sgemm<0><<<dim3(8, 64, 1), 256>>>(x1, wv, vb,
        BL, DD, DD, DD, DD, DD, 0,0,0,0,0,0, 1, 1.0f, nullptr, nullptr, 0);

    // 8. scores[b,h] = Q_bh @ K_bhᵀ   (batched NT, K=64)
    sgemm<1><<<dim3(16, 16, BB*HH), 256>>>(q, kb, sc,
        LL, LL, HDIM, DD, DD, LL,
        LLD, 64, LLD, 64, (long long)HH*LL2, LL2, HH,
        1.0f, nullptr, nullptr, 0);

    // 9. softmax rows
    softmax_kernel<<<BB*HH*LL, 256>>>(sc);

    // 10. att[b,q,h,:] = P_bh @ V_bh   (batched NN, N=64)
    sgemm<0><<<dim3(1, 16, BB*HH), 256>>>(sc, vb, att,
        LL, HDIM, LL, LL, DD, DD,
        (long long)HH*LL2, LL2, LLD, 64, LLD, 64, HH,
        1.0f, nullptr, nullptr, 0);

    // 11. x = att @ wo + stu
    sgemm<0><<<dim3(8, 64, 1), 256>>>(att, wo, xres,
        BL, DD, DD, DD, DD, DD, 0,0,0,0,0,0, 1, 1.0f, nullptr, stu, 4);

    // 12. LN2
    ln_kernel<<<BL, 256>>>(xres, y1, ln2_s, ln2_b);

    // 13. h = gelu(y1 @ mlp_w1 + b1)
    sgemm<0><<<dim3(MLPD/128, 64, 1), 256>>>(y1, mlp_w1, hbuf,
        BL, MLPD, DD, DD, MLPD, MLPD, 0,0,0,0,0,0, 1, 1.0f, mlp_b1, nullptr, 3);

    // 14. out = h @ mlp_w2 + b2 + x
    sgemm<0><<<dim3(8, 64, 1), 256>>>(hbuf, mlp_w2, out,
        BL, DD, MLPD, MLPD, DD, DD, 0,0,0,0,0,0, 1, 1.0f, mlp_b2, xres, 5);
}